// round 8
// baseline (speedup 1.0000x reference)
#include <cuda_runtime.h>
#include <cuda_bf16.h>

// Gather word-offsets (two-choice balanced) and prescaled G.
__device__ __align__(16) int   g_P2[8192];
__device__ __align__(16) float g_Gs[8192];

__host__ __device__ __forceinline__ int mapA(int q) {
    return q ^ ((q >> 4) & 28);
}
__host__ __device__ __forceinline__ int mapB(int q) {
    return q ^ ((q >> 4) & 28) ^ ((q >> 7) & 28) ^ ((q >> 4) & 2);
}

// One thread per gather instruction group (256 groups of 32 lanes).
// Two-choice greedy bank balancing + repair; duplicates forced to broadcast.
__global__ void setup_gather(const int* __restrict__ P) {
    int g = blockIdx.x * 32 + threadIdx.x;
    if (g >= 256) return;
    int W = g >> 5, rh = (g >> 2) & 7, c = g & 3;

    int q[32], bA[32], bB[32], sel[32], counts[32];
#pragma unroll
    for (int b = 0; b < 32; b++) counts[b] = 0;

    for (int L = 0; L < 32; L++) {
        int e = (W << 10) | (rh << 7) | (L << 2) | c;
        q[L]  = P[e] & 4095;
        bA[L] = mapA(q[L]) & 31;
        bB[L] = mapB(q[L]) & 31;
    }
    // greedy (skip counting duplicates: same word -> broadcast)
    for (int L = 0; L < 32; L++) {
        int dup = -1;
        for (int j = 0; j < L; j++) if (q[j] == q[L]) { dup = j; break; }
        if (dup >= 0) { sel[L] = sel[dup]; continue; }
        sel[L] = (counts[bB[L]] < counts[bA[L]]) ? 1 : 0;
        counts[sel[L] ? bB[L] : bA[L]]++;
    }
    // repair passes
    for (int pass = 0; pass < 3; pass++) {
        for (int L = 0; L < 32; L++) {
            bool isdup = false;
            for (int j = 0; j < L; j++) if (q[j] == q[L]) { isdup = true; break; }
            if (isdup) continue;
            int cur = sel[L] ? bB[L] : bA[L];
            int alt = sel[L] ? bA[L] : bB[L];
            if (counts[cur] > counts[alt] + 1) {
                counts[cur]--; counts[alt]++; sel[L] ^= 1;
            }
        }
    }
    // re-sync duplicates to their representative (broadcast guarantee)
    for (int L = 0; L < 32; L++)
        for (int j = 0; j < L; j++)
            if (q[j] == q[L]) { sel[L] = sel[j]; break; }

    for (int L = 0; L < 32; L++) {
        int e = (W << 10) | (rh << 7) | (L << 2) | c;
        g_P2[e] = sel[L] ? (4096 + mapB(q[L])) : mapA(q[L]);
    }
}

__global__ void setup_g(const float* __restrict__ G) {
    int e = blockIdx.x * 256 + threadIdx.x;
    g_Gs[e] = G[e] * (1.0f / 8192.0f);   // both 1/sqrt(8192) factors folded
}

// In-register butterfly stage over register-index bit MASK, N registers.
template <int N, int MASK>
__device__ __forceinline__ void stage(float* v) {
#pragma unroll
    for (int i = 0; i < N; i++) {
        if (!(i & MASK)) {
            float a = v[i], b = v[i ^ MASK];
            v[i] = a + b;
            v[i ^ MASK] = a - b;
        }
    }
}

// One CTA per row, 256 threads (8 warps). Phase 1: 4096-pt FWHT of x*B
// (H_8192[y;0] = [H_4096 y; H_4096 y]). Phase 2: perm-gather * G, 8192-pt FWHT.
// All shared patterns bank-conflict-free; gather conflicts minimized by
// two-choice replication (copy A words [0,4096), copy B words [4096,8192)).
__global__ __launch_bounds__(256, 4) void fastfood_kernel(
    const float4* __restrict__ x4,   // (rows, 1024) float4
    const float4* __restrict__ B4,   // 2048 float4 (first 1024 used)
    float4* __restrict__ out4,       // (rows, 2048) float4
    int rows)
{
    __shared__ float sh[8192];                       // 32 KB
    float4* sh4 = reinterpret_cast<float4*>(sh);

    const int row = blockIdx.x;
    if (row >= rows) return;
    const int T = threadIdx.x;
    const int W = T >> 5, L = T & 31;
    const int L10 = L & 3, L42 = L >> 2, L210 = L & 7, L43 = L >> 3;
    const int W10 = W >> 1, W0 = W & 1;

    float v[32];

    // ============ Phase 1: 4096-pt FWHT, i[11:0] ============
    // A1: regs=(rh,c): c=i[1:0], rh=i[11:10]; lanes=i[6:2]; warp=i[9:7]
    {
        const float4* xr = x4 + (size_t)row * 1024;
#pragma unroll
        for (int rh = 0; rh < 4; rh++) {
            int idx = (rh << 8) | (W << 5) | L;      // = i>>2, coalesced
            float4 xv = xr[idx], bv = B4[idx];
            v[rh * 4 + 0] = xv.x * bv.x;
            v[rh * 4 + 1] = xv.y * bv.y;
            v[rh * 4 + 2] = xv.z * bv.z;
            v[rh * 4 + 3] = xv.w * bv.w;
        }
    }
    stage<16, 1>(v); stage<16, 2>(v); stage<16, 4>(v); stage<16, 8>(v); // i 0,1,10,11

    // W1 (vector, identity map): slot = i>>2.
#pragma unroll
    for (int rh = 0; rh < 4; rh++)
        sh4[(rh << 8) | (W << 5) | L] =
            make_float4(v[rh * 4 + 0], v[rh * 4 + 1], v[rh * 4 + 2], v[rh * 4 + 3]);
    __syncthreads();

    // R1 (scalar): regs=i[8:5], lanes=i[4:0], warp=i[11:9]. word = i.
    {
        int base = (W << 9) | L;
#pragma unroll
        for (int r = 0; r < 16; r++) v[r] = sh[base + (r << 5)];
    }
    stage<16, 1>(v); stage<16, 2>(v); stage<16, 4>(v); stage<16, 8>(v); // i 5,6,7,8
    __syncthreads();

    // W2 (scalar, mapA(i) = i ^ (i[8:6]<<2); i[8:6]=r[3:1])
    {
        int base = (W << 9) | L;
#pragma unroll
        for (int r = 0; r < 16; r++)
            sh[base ^ ((r << 5) | (((r >> 1) & 7) << 2))] = v[r];
    }
    __syncthreads();

    // R2 (scalar, mapA): regs r210=i[4:2], r3=i9; lanes L10=i[1:0], L42=i[8:6];
    //                    warp W0=i5, W21=i[11:10]. word = i ^ (L42<<2).
    int base_r2 = (W10 << 10) | (L42 << 6) | (W0 << 5) | (L42 << 2) | L10;
#pragma unroll
    for (int r = 0; r < 16; r++)
        v[r] = sh[base_r2 ^ ((((r >> 3) & 1) << 9) | ((r & 7) << 2))];
    stage<16, 1>(v); stage<16, 2>(v); stage<16, 4>(v); stage<16, 8>(v); // i 2,3,4,9

    // W3: copy A at mapA(i) (same addresses just read -> no pre-sync),
    //     copy B at 4096+mapB(i) (upper half untouched in phase 1 -> no hazard).
    {
        int baseB = ((4096 | (W10 << 10) | (L42 << 6) | (W0 << 5) | L10))
                    ^ (L42 << 2) ^ (W10 << 3) ^ (W0 << 1);
#pragma unroll
        for (int r = 0; r < 16; r++) {
            sh[base_r2 ^ ((((r >> 3) & 1) << 9) | ((r & 7) << 2))] = v[r];
            sh[baseB  ^ ((((r >> 3) & 1) << 9) | ((((r & 7) ^ (r >> 3)) & 7) << 2))] = v[r];
        }
    }
    __syncthreads();

    // ============ Permutation + G (two-choice precomputed offsets) ============
    // A2: e = (W<<10)|(rh<<7)|(L<<2)|c ; regs=(rh,c): c=e[1:0], rh=e[9:7]
    {
        const int4*   P2_4 = reinterpret_cast<const int4*>(g_P2);
        const float4* G4s  = reinterpret_cast<const float4*>(g_Gs);
#pragma unroll
        for (int rh = 0; rh < 8; rh++) {
            int meta = (W << 8) | (rh << 5) | L;     // = e>>2, coalesced
            int4  p = P2_4[meta];
            float4 g = G4s[meta];
            v[rh * 4 + 0] = sh[p.x] * g.x;
            v[rh * 4 + 1] = sh[p.y] * g.y;
            v[rh * 4 + 2] = sh[p.z] * g.z;
            v[rh * 4 + 3] = sh[p.w] * g.w;
        }
    }
    __syncthreads();   // all gathers done before W4 overwrites

    // ============ Phase 2: 8192-pt FWHT, e[12:0] ============
    stage<32, 1>(v); stage<32, 2>(v); stage<32, 4>(v);
    stage<32, 8>(v); stage<32, 16>(v);               // e 0,1,7,8,9

    // Storage map for trips 4/5:
    // w(e) = (e[12:10]<<10)|(e[6:5]<<8)|(e[9:7]<<5)|((e[4:2]^e[9:7])<<2)|e[1:0]
    // W4 (vector): slot = (W<<8)|(L43<<6)|(rh<<3)|(L210^rh).
    {
        int baseW4 = (W << 8) | (L43 << 6) | L210;
#pragma unroll
        for (int rh = 0; rh < 8; rh++)
            sh4[baseW4 ^ (rh * 9)] =
                make_float4(v[rh * 4 + 0], v[rh * 4 + 1], v[rh * 4 + 2], v[rh * 4 + 3]);
    }
    __syncthreads();

    // R4 (scalar): regs r=e[6:2]; lanes L10=e[1:0], L42=e[9:7]; warp=e[12:10].
    int baseR4 = (W << 10) | (L42 << 5) | (L42 << 2) | L10;
#pragma unroll
    for (int r = 0; r < 32; r++)
        v[r] = sh[baseR4 ^ (((r >> 3) << 8) | ((r & 7) << 2))];
    stage<32, 1>(v); stage<32, 2>(v); stage<32, 4>(v);
    stage<32, 8>(v); stage<32, 16>(v);               // e 2,3,4,5,6
    // W5: same addresses (no pre-sync).
#pragma unroll
    for (int r = 0; r < 32; r++)
        sh[baseR4 ^ (((r >> 3) << 8) | ((r & 7) << 2))] = v[r];
    __syncthreads();

    // R5 (vector): regs=(rp,c): c=e[1:0], rp=e[12:10]; lanes=e[6:2]; warp=e[9:7].
    {
        int baseR5 = (L43 << 6) | (W << 3) | (L210 ^ W);
#pragma unroll
        for (int rp = 0; rp < 8; rp++) {
            float4 t = sh4[baseR5 + (rp << 8)];
            v[rp * 4 + 0] = t.x; v[rp * 4 + 1] = t.y;
            v[rp * 4 + 2] = t.z; v[rp * 4 + 3] = t.w;
        }
    }
    stage<32, 4>(v); stage<32, 8>(v); stage<32, 16>(v); // e 10,11,12

    // ============ Coalesced store (scale already folded into G) ============
#pragma unroll
    for (int rp = 0; rp < 8; rp++)
        out4[(size_t)row * 2048 + (rp << 8) + (W << 5) + L] =
            make_float4(v[rp * 4 + 0], v[rp * 4 + 1],
                        v[rp * 4 + 2], v[rp * 4 + 3]);
}

extern "C" void kernel_launch(void* const* d_in, const int* in_sizes, int n_in,
                              void* d_out, int out_size) {
    const float* x = (const float*)d_in[0];
    const float* B = (const float*)d_in[1];
    const float* G = (const float*)d_in[2];
    const int*   P = (const int*)d_in[3];
    float* out = (float*)d_out;

    int rows = in_sizes[0] / 4096;

    setup_gather<<<8, 32>>>(P);
    setup_g<<<32, 256>>>(G);
    fastfood_kernel<<<rows, 256>>>(
        (const float4*)x, (const float4*)B, (float4*)out, rows);
}

// round 9
// speedup vs baseline: 1.0779x; 1.0779x over previous
#include <cuda_runtime.h>
#include <cuda_bf16.h>

// Gather word-offsets (two-choice balanced) and prescaled G.
__device__ __align__(16) int   g_P2[8192];
__device__ __align__(16) float g_Gs[8192];

__host__ __device__ __forceinline__ int mapA(int q) {
    return q ^ ((q >> 4) & 28);
}
__host__ __device__ __forceinline__ int mapB(int q) {
    return q ^ ((q >> 4) & 28) ^ ((q >> 7) & 28) ^ ((q >> 4) & 2);
}

// One WARP per gather instruction group (256 groups). Two-choice greedy bank
// balancing + repair, serialized over lanes via per-warp shared counters.
// Duplicate words resolved to one copy (broadcast). Also prescales G.
__global__ void setup_kernel(const int* __restrict__ P,
                             const float* __restrict__ G) {
    const int tid  = blockIdx.x * 256 + threadIdx.x;
    g_Gs[tid] = G[tid] * (1.0f / 8192.0f);   // both 1/sqrt(8192) factors folded

    const int g    = tid >> 5;               // group id 0..255
    const int lane = threadIdx.x & 31;
    const int wib  = threadIdx.x >> 5;       // warp in block

    const int W = g >> 5, rh = (g >> 2) & 7, c = g & 3;
    const int e = (W << 10) | (rh << 7) | (lane << 2) | c;
    const int q = P[e] & 4095;
    const int a = mapA(q), b = mapB(q);
    const int bA = a & 31, bB = b & 31;

    // duplicate detection: representative = lowest lane with equal q
    unsigned same = __match_any_sync(0xffffffffu, q);
    const int  rep   = __ffs(same) - 1;
    const bool isrep = (rep == lane);

    __shared__ int counts[8][32];
    counts[wib][lane] = 0;
    __syncwarp();

    int sel = 0;
    // greedy pass (serialized over lanes; each step is O(1))
    for (int i = 0; i < 32; i++) {
        if (lane == i && isrep) {
            sel = (counts[wib][bB] < counts[wib][bA]) ? 1 : 0;
            counts[wib][sel ? bB : bA]++;
        }
        __syncwarp();
    }
    // repair passes
    for (int pass = 0; pass < 3; pass++) {
        for (int i = 0; i < 32; i++) {
            if (lane == i && isrep) {
                int cur = sel ? bB : bA;
                int alt = sel ? bA : bB;
                if (counts[wib][cur] > counts[wib][alt] + 1) {
                    counts[wib][cur]--; counts[wib][alt]++; sel ^= 1;
                }
            }
            __syncwarp();
        }
    }
    // duplicates follow their representative (guarantees broadcast)
    sel = __shfl_sync(0xffffffffu, sel, rep);

    g_P2[e] = sel ? (4096 + b) : a;
}

// In-register butterfly stage over register-index bit MASK, N registers.
template <int N, int MASK>
__device__ __forceinline__ void stage(float* v) {
#pragma unroll
    for (int i = 0; i < N; i++) {
        if (!(i & MASK)) {
            float a = v[i], b = v[i ^ MASK];
            v[i] = a + b;
            v[i ^ MASK] = a - b;
        }
    }
}

// One CTA per row, 256 threads (8 warps). Phase 1: 4096-pt FWHT of x*B
// (H_8192[y;0] = [H_4096 y; H_4096 y]). Phase 2: perm-gather * G, 8192-pt FWHT.
// All shared patterns bank-conflict-free; gather conflicts minimized by
// two-choice replication (copy A words [0,4096), copy B words [4096,8192)).
__global__ __launch_bounds__(256, 4) void fastfood_kernel(
    const float4* __restrict__ x4,   // (rows, 1024) float4
    const float4* __restrict__ B4,   // 2048 float4 (first 1024 used)
    float4* __restrict__ out4,       // (rows, 2048) float4
    int rows)
{
    __shared__ float sh[8192];                       // 32 KB
    float4* sh4 = reinterpret_cast<float4*>(sh);

    const int row = blockIdx.x;
    if (row >= rows) return;
    const int T = threadIdx.x;
    const int W = T >> 5, L = T & 31;
    const int L10 = L & 3, L42 = L >> 2, L210 = L & 7, L43 = L >> 3;
    const int W10 = W >> 1, W0 = W & 1;

    float v[32];

    // ============ Phase 1: 4096-pt FWHT, i[11:0] ============
    // A1: regs=(rh,c): c=i[1:0], rh=i[11:10]; lanes=i[6:2]; warp=i[9:7]
    {
        const float4* xr = x4 + (size_t)row * 1024;
#pragma unroll
        for (int rh = 0; rh < 4; rh++) {
            int idx = (rh << 8) | (W << 5) | L;      // = i>>2, coalesced
            float4 xv = xr[idx], bv = B4[idx];
            v[rh * 4 + 0] = xv.x * bv.x;
            v[rh * 4 + 1] = xv.y * bv.y;
            v[rh * 4 + 2] = xv.z * bv.z;
            v[rh * 4 + 3] = xv.w * bv.w;
        }
    }
    stage<16, 1>(v); stage<16, 2>(v); stage<16, 4>(v); stage<16, 8>(v); // i 0,1,10,11

    // W1 (vector, identity map): slot = i>>2.
#pragma unroll
    for (int rh = 0; rh < 4; rh++)
        sh4[(rh << 8) | (W << 5) | L] =
            make_float4(v[rh * 4 + 0], v[rh * 4 + 1], v[rh * 4 + 2], v[rh * 4 + 3]);
    __syncthreads();

    // R1 (scalar): regs=i[8:5], lanes=i[4:0], warp=i[11:9]. word = i.
    {
        int base = (W << 9) | L;
#pragma unroll
        for (int r = 0; r < 16; r++) v[r] = sh[base + (r << 5)];
    }
    stage<16, 1>(v); stage<16, 2>(v); stage<16, 4>(v); stage<16, 8>(v); // i 5,6,7,8
    __syncthreads();

    // W2 (scalar, mapA(i) = i ^ (i[8:6]<<2); i[8:6]=r[3:1])
    {
        int base = (W << 9) | L;
#pragma unroll
        for (int r = 0; r < 16; r++)
            sh[base ^ ((r << 5) | (((r >> 1) & 7) << 2))] = v[r];
    }
    __syncthreads();

    // R2 (scalar, mapA): regs r210=i[4:2], r3=i9; lanes L10=i[1:0], L42=i[8:6];
    //                    warp W0=i5, W21=i[11:10]. word = i ^ (L42<<2).
    int base_r2 = (W10 << 10) | (L42 << 6) | (W0 << 5) | (L42 << 2) | L10;
#pragma unroll
    for (int r = 0; r < 16; r++)
        v[r] = sh[base_r2 ^ ((((r >> 3) & 1) << 9) | ((r & 7) << 2))];
    stage<16, 1>(v); stage<16, 2>(v); stage<16, 4>(v); stage<16, 8>(v); // i 2,3,4,9

    // W3: copy A at mapA(i) (same addresses just read -> no pre-sync),
    //     copy B at 4096+mapB(i) (upper half untouched in phase 1 -> no hazard).
    {
        int baseB = ((4096 | (W10 << 10) | (L42 << 6) | (W0 << 5) | L10))
                    ^ (L42 << 2) ^ (W10 << 3) ^ (W0 << 1);
#pragma unroll
        for (int r = 0; r < 16; r++) {
            sh[base_r2 ^ ((((r >> 3) & 1) << 9) | ((r & 7) << 2))] = v[r];
            sh[baseB  ^ ((((r >> 3) & 1) << 9) | ((((r & 7) ^ (r >> 3)) & 7) << 2))] = v[r];
        }
    }
    __syncthreads();

    // ============ Permutation + G (two-choice precomputed offsets) ============
    // A2: e = (W<<10)|(rh<<7)|(L<<2)|c ; regs=(rh,c): c=e[1:0], rh=e[9:7]
    {
        const int4*   P2_4 = reinterpret_cast<const int4*>(g_P2);
        const float4* G4s  = reinterpret_cast<const float4*>(g_Gs);
#pragma unroll
        for (int rh = 0; rh < 8; rh++) {
            int meta = (W << 8) | (rh << 5) | L;     // = e>>2, coalesced
            int4  p = P2_4[meta];
            float4 g = G4s[meta];
            v[rh * 4 + 0] = sh[p.x] * g.x;
            v[rh * 4 + 1] = sh[p.y] * g.y;
            v[rh * 4 + 2] = sh[p.z] * g.z;
            v[rh * 4 + 3] = sh[p.w] * g.w;
        }
    }
    __syncthreads();   // all gathers done before W4 overwrites

    // ============ Phase 2: 8192-pt FWHT, e[12:0] ============
    stage<32, 1>(v); stage<32, 2>(v); stage<32, 4>(v);
    stage<32, 8>(v); stage<32, 16>(v);               // e 0,1,7,8,9

    // Storage map for trips 4/5:
    // w(e) = (e[12:10]<<10)|(e[6:5]<<8)|(e[9:7]<<5)|((e[4:2]^e[9:7])<<2)|e[1:0]
    // W4 (vector): slot = (W<<8)|(L43<<6)|(rh<<3)|(L210^rh).
    {
        int baseW4 = (W << 8) | (L43 << 6) | L210;
#pragma unroll
        for (int rh = 0; rh < 8; rh++)
            sh4[baseW4 ^ (rh * 9)] =
                make_float4(v[rh * 4 + 0], v[rh * 4 + 1], v[rh * 4 + 2], v[rh * 4 + 3]);
    }
    __syncthreads();

    // R4 (scalar): regs r=e[6:2]; lanes L10=e[1:0], L42=e[9:7]; warp=e[12:10].
    int baseR4 = (W << 10) | (L42 << 5) | (L42 << 2) | L10;
#pragma unroll
    for (int r = 0; r < 32; r++)
        v[r] = sh[baseR4 ^ (((r >> 3) << 8) | ((r & 7) << 2))];
    stage<32, 1>(v); stage<32, 2>(v); stage<32, 4>(v);
    stage<32, 8>(v); stage<32, 16>(v);               // e 2,3,4,5,6
    // W5: same addresses (no pre-sync).
#pragma unroll
    for (int r = 0; r < 32; r++)
        sh[baseR4 ^ (((r >> 3) << 8) | ((r & 7) << 2))] = v[r];
    __syncthreads();

    // R5 (vector): regs=(rp,c): c=e[1:0], rp=e[12:10]; lanes=e[6:2]; warp=e[9:7].
    {
        int baseR5 = (L43 << 6) | (W << 3) | (L210 ^ W);
#pragma unroll
        for (int rp = 0; rp < 8; rp++) {
            float4 t = sh4[baseR5 + (rp << 8)];
            v[rp * 4 + 0] = t.x; v[rp * 4 + 1] = t.y;
            v[rp * 4 + 2] = t.z; v[rp * 4 + 3] = t.w;
        }
    }
    stage<32, 4>(v); stage<32, 8>(v); stage<32, 16>(v); // e 10,11,12

    // ============ Coalesced store (scale already folded into G) ============
#pragma unroll
    for (int rp = 0; rp < 8; rp++)
        out4[(size_t)row * 2048 + (rp << 8) + (W << 5) + L] =
            make_float4(v[rp * 4 + 0], v[rp * 4 + 1],
                        v[rp * 4 + 2], v[rp * 4 + 3]);
}

extern "C" void kernel_launch(void* const* d_in, const int* in_sizes, int n_in,
                              void* d_out, int out_size) {
    const float* x = (const float*)d_in[0];
    const float* B = (const float*)d_in[1];
    const float* G = (const float*)d_in[2];
    const int*   P = (const int*)d_in[3];
    float* out = (float*)d_out;

    int rows = in_sizes[0] / 4096;

    setup_kernel<<<32, 256>>>(P, G);
    fastfood_kernel<<<rows, 256>>>(
        (const float4*)x, (const float4*)B, (float4*)out, rows);
}

// round 10
// speedup vs baseline: 1.1441x; 1.0615x over previous
#include <cuda_runtime.h>
#include <cuda_bf16.h>

// Gather word-offsets (two-choice balanced) and prescaled G.
__device__ __align__(16) int   g_P2[8192];
__device__ __align__(16) float g_Gs[8192];

__host__ __device__ __forceinline__ int mapA(int q) {
    return q ^ ((q >> 4) & 28);
}
__host__ __device__ __forceinline__ int mapB(int q) {
    return q ^ ((q >> 4) & 28) ^ ((q >> 7) & 28) ^ ((q >> 4) & 2);
}

// One WARP per gather instruction group (256 groups). Parallel iterative
// two-choice bank balancing: each round, every overloaded bank sheds its
// lowest-lane member to that member's alternate bank. 8 rounds, all lanes
// parallel (shared atomics + ballot/match leader election). Duplicate words
// resolved to one copy (broadcast). Also prescales G by 1/8192.
__global__ void setup_kernel(const int* __restrict__ P,
                             const float* __restrict__ G) {
    const int tid  = blockIdx.x * 256 + threadIdx.x;
    g_Gs[tid] = G[tid] * (1.0f / 8192.0f);   // both 1/sqrt(8192) factors folded

    const int g    = tid >> 5;               // group id 0..255
    const int lane = threadIdx.x & 31;
    const int wib  = threadIdx.x >> 5;       // warp in block

    const int W = g >> 5, rh = (g >> 2) & 7, c = g & 3;
    const int e = (W << 10) | (rh << 7) | (lane << 2) | c;
    const int q = P[e] & 4095;
    const int a = mapA(q), b = mapB(q);
    const int bA = a & 31, bB = b & 31;

    // duplicate detection: representative = lowest lane with equal q
    unsigned same = __match_any_sync(0xffffffffu, q);
    const int  rep   = __ffs(same) - 1;
    const bool isrep = (rep == lane);

    __shared__ int counts[8][32];

    int sel = 0;
#pragma unroll
    for (int it = 0; it < 8; it++) {
        counts[wib][lane] = 0;
        __syncwarp();
        const int cur = sel ? bB : bA;
        const int alt = sel ? bA : bB;
        if (isrep) atomicAdd(&counts[wib][cur], 1);
        __syncwarp();
        const int  lc   = counts[wib][cur];
        const int  la   = counts[wib][alt];
        const bool want = isrep && (lc > la + 1);
        const unsigned wm   = __ballot_sync(0xffffffffu, want);
        const unsigned curm = __match_any_sync(0xffffffffu, cur);
        // only the lowest wanting lane per current-bank flips this round
        if (want && lane == (__ffs(wm & curm) - 1)) sel ^= 1;
        __syncwarp();
    }
    // duplicates follow their representative (guarantees broadcast)
    sel = __shfl_sync(0xffffffffu, sel, rep);

    g_P2[e] = sel ? (4096 + b) : a;
}

// In-register butterfly stage over register-index bit MASK, N registers.
template <int N, int MASK>
__device__ __forceinline__ void stage(float* v) {
#pragma unroll
    for (int i = 0; i < N; i++) {
        if (!(i & MASK)) {
            float a = v[i], b = v[i ^ MASK];
            v[i] = a + b;
            v[i ^ MASK] = a - b;
        }
    }
}

// One CTA per row, 256 threads (8 warps). Phase 1: 4096-pt FWHT of x*B
// (H_8192[y;0] = [H_4096 y; H_4096 y]). Phase 2: perm-gather * G, 8192-pt FWHT.
// All shared patterns bank-conflict-free; gather conflicts minimized by
// two-choice replication (copy A words [0,4096), copy B words [4096,8192)).
__global__ __launch_bounds__(256, 4) void fastfood_kernel(
    const float4* __restrict__ x4,   // (rows, 1024) float4
    const float4* __restrict__ B4,   // 2048 float4 (first 1024 used)
    float4* __restrict__ out4,       // (rows, 2048) float4
    int rows)
{
    __shared__ float sh[8192];                       // 32 KB
    float4* sh4 = reinterpret_cast<float4*>(sh);

    const int row = blockIdx.x;
    if (row >= rows) return;
    const int T = threadIdx.x;
    const int W = T >> 5, L = T & 31;
    const int L10 = L & 3, L42 = L >> 2, L210 = L & 7, L43 = L >> 3;
    const int W10 = W >> 1, W0 = W & 1;

    float v[32];

    // ============ Phase 1: 4096-pt FWHT, i[11:0] ============
    // A1: regs=(rh,c): c=i[1:0], rh=i[11:10]; lanes=i[6:2]; warp=i[9:7]
    {
        const float4* xr = x4 + (size_t)row * 1024;
#pragma unroll
        for (int rh = 0; rh < 4; rh++) {
            int idx = (rh << 8) | (W << 5) | L;      // = i>>2, coalesced
            float4 xv = xr[idx], bv = B4[idx];
            v[rh * 4 + 0] = xv.x * bv.x;
            v[rh * 4 + 1] = xv.y * bv.y;
            v[rh * 4 + 2] = xv.z * bv.z;
            v[rh * 4 + 3] = xv.w * bv.w;
        }
    }
    stage<16, 1>(v); stage<16, 2>(v); stage<16, 4>(v); stage<16, 8>(v); // i 0,1,10,11

    // W1 (vector, identity map): slot = i>>2.
#pragma unroll
    for (int rh = 0; rh < 4; rh++)
        sh4[(rh << 8) | (W << 5) | L] =
            make_float4(v[rh * 4 + 0], v[rh * 4 + 1], v[rh * 4 + 2], v[rh * 4 + 3]);
    __syncthreads();

    // R1 (scalar): regs=i[8:5], lanes=i[4:0], warp=i[11:9]. word = i.
    {
        int base = (W << 9) | L;
#pragma unroll
        for (int r = 0; r < 16; r++) v[r] = sh[base + (r << 5)];
    }
    stage<16, 1>(v); stage<16, 2>(v); stage<16, 4>(v); stage<16, 8>(v); // i 5,6,7,8
    __syncthreads();

    // W2 (scalar, mapA(i) = i ^ (i[8:6]<<2); i[8:6]=r[3:1])
    {
        int base = (W << 9) | L;
#pragma unroll
        for (int r = 0; r < 16; r++)
            sh[base ^ ((r << 5) | (((r >> 1) & 7) << 2))] = v[r];
    }
    __syncthreads();

    // R2 (scalar, mapA): regs r210=i[4:2], r3=i9; lanes L10=i[1:0], L42=i[8:6];
    //                    warp W0=i5, W21=i[11:10]. word = i ^ (L42<<2).
    int base_r2 = (W10 << 10) | (L42 << 6) | (W0 << 5) | (L42 << 2) | L10;
#pragma unroll
    for (int r = 0; r < 16; r++)
        v[r] = sh[base_r2 ^ ((((r >> 3) & 1) << 9) | ((r & 7) << 2))];
    stage<16, 1>(v); stage<16, 2>(v); stage<16, 4>(v); stage<16, 8>(v); // i 2,3,4,9

    // W3: copy A at mapA(i) (same addresses just read -> no pre-sync),
    //     copy B at 4096+mapB(i) (upper half untouched in phase 1 -> no hazard).
    {
        int baseB = ((4096 | (W10 << 10) | (L42 << 6) | (W0 << 5) | L10))
                    ^ (L42 << 2) ^ (W10 << 3) ^ (W0 << 1);
#pragma unroll
        for (int r = 0; r < 16; r++) {
            sh[base_r2 ^ ((((r >> 3) & 1) << 9) | ((r & 7) << 2))] = v[r];
            sh[baseB  ^ ((((r >> 3) & 1) << 9) | ((((r & 7) ^ (r >> 3)) & 7) << 2))] = v[r];
        }
    }
    __syncthreads();

    // ============ Permutation + G (two-choice precomputed offsets) ============
    // A2: e = (W<<10)|(rh<<7)|(L<<2)|c ; regs=(rh,c): c=e[1:0], rh=e[9:7]
    {
        const int4*   P2_4 = reinterpret_cast<const int4*>(g_P2);
        const float4* G4s  = reinterpret_cast<const float4*>(g_Gs);
#pragma unroll
        for (int rh = 0; rh < 8; rh++) {
            int meta = (W << 8) | (rh << 5) | L;     // = e>>2, coalesced
            int4  p = P2_4[meta];
            float4 g = G4s[meta];
            v[rh * 4 + 0] = sh[p.x] * g.x;
            v[rh * 4 + 1] = sh[p.y] * g.y;
            v[rh * 4 + 2] = sh[p.z] * g.z;
            v[rh * 4 + 3] = sh[p.w] * g.w;
        }
    }
    __syncthreads();   // all gathers done before W4 overwrites

    // ============ Phase 2: 8192-pt FWHT, e[12:0] ============
    stage<32, 1>(v); stage<32, 2>(v); stage<32, 4>(v);
    stage<32, 8>(v); stage<32, 16>(v);               // e 0,1,7,8,9

    // Storage map for trips 4/5:
    // w(e) = (e[12:10]<<10)|(e[6:5]<<8)|(e[9:7]<<5)|((e[4:2]^e[9:7])<<2)|e[1:0]
    // W4 (vector): slot = (W<<8)|(L43<<6)|(rh<<3)|(L210^rh).
    {
        int baseW4 = (W << 8) | (L43 << 6) | L210;
#pragma unroll
        for (int rh = 0; rh < 8; rh++)
            sh4[baseW4 ^ (rh * 9)] =
                make_float4(v[rh * 4 + 0], v[rh * 4 + 1], v[rh * 4 + 2], v[rh * 4 + 3]);
    }
    __syncthreads();

    // R4 (scalar): regs r=e[6:2]; lanes L10=e[1:0], L42=e[9:7]; warp=e[12:10].
    int baseR4 = (W << 10) | (L42 << 5) | (L42 << 2) | L10;
#pragma unroll
    for (int r = 0; r < 32; r++)
        v[r] = sh[baseR4 ^ (((r >> 3) << 8) | ((r & 7) << 2))];
    stage<32, 1>(v); stage<32, 2>(v); stage<32, 4>(v);
    stage<32, 8>(v); stage<32, 16>(v);               // e 2,3,4,5,6
    // W5: same addresses (no pre-sync).
#pragma unroll
    for (int r = 0; r < 32; r++)
        sh[baseR4 ^ (((r >> 3) << 8) | ((r & 7) << 2))] = v[r];
    __syncthreads();

    // R5 (vector): regs=(rp,c): c=e[1:0], rp=e[12:10]; lanes=e[6:2]; warp=e[9:7].
    {
        int baseR5 = (L43 << 6) | (W << 3) | (L210 ^ W);
#pragma unroll
        for (int rp = 0; rp < 8; rp++) {
            float4 t = sh4[baseR5 + (rp << 8)];
            v[rp * 4 + 0] = t.x; v[rp * 4 + 1] = t.y;
            v[rp * 4 + 2] = t.z; v[rp * 4 + 3] = t.w;
        }
    }
    stage<32, 4>(v); stage<32, 8>(v); stage<32, 16>(v); // e 10,11,12

    // ============ Coalesced store (scale already folded into G) ============
#pragma unroll
    for (int rp = 0; rp < 8; rp++)
        out4[(size_t)row * 2048 + (rp << 8) + (W << 5) + L] =
            make_float4(v[rp * 4 + 0], v[rp * 4 + 1],
                        v[rp * 4 + 2], v[rp * 4 + 3]);
}

extern "C" void kernel_launch(void* const* d_in, const int* in_sizes, int n_in,
                              void* d_out, int out_size) {
    const float* x = (const float*)d_in[0];
    const float* B = (const float*)d_in[1];
    const float* G = (const float*)d_in[2];
    const int*   P = (const int*)d_in[3];
    float* out = (float*)d_out;

    int rows = in_sizes[0] / 4096;

    setup_kernel<<<32, 256>>>(P, G);
    fastfood_kernel<<<rows, 256>>>(
        (const float4*)x, (const float4*)B, (float4*)out, rows);
}